// round 7
// baseline (speedup 1.0000x reference)
#include <cuda_runtime.h>
#include <math.h>
#include <stdint.h>

#define B_  2
#define S_  2048
#define E_  1024
#define H_  16
#define HD_ 64

// Scratch (allocation-free: __device__ globals)
__device__ float g_Q[B_*H_*S_*HD_];   // tf32-rounded, pre-scaled by 0.125*log2(e)
__device__ float g_K[B_*H_*S_*HD_];   // tf32-rounded
__device__ float g_V[B_*H_*S_*HD_];   // tf32-rounded
__device__ float g_O[B_*S_*E_];       // attention out, tf32-rounded (proj A input)
__device__ float g_Xr[B_*S_*E_];      // tf32-rounded x
__device__ float g_Wq[3*E_*E_];       // tf32-rounded w_qkv
__device__ float g_Wp[E_*E_];         // tf32-rounded w_proj

// ============================================================================
// PTX helpers (plain sm_80+ ISA — no 'a'-suffix features)
// ============================================================================
__device__ __forceinline__ float tf32_rna(float x) {
    uint32_t r;
    asm("cvt.rna.tf32.f32 %0, %1;" : "=r"(r) : "f"(x));
    return __uint_as_float(r);
}

__device__ __forceinline__ void mma_tf32(float4& d,
                                         uint32_t a0, uint32_t a1, uint32_t a2, uint32_t a3,
                                         uint32_t b0, uint32_t b1)
{
    asm volatile(
        "mma.sync.aligned.m16n8k8.row.col.f32.tf32.tf32.f32 "
        "{%0,%1,%2,%3}, {%4,%5,%6,%7}, {%8,%9}, {%0,%1,%2,%3};"
        : "+f"(d.x), "+f"(d.y), "+f"(d.z), "+f"(d.w)
        : "r"(a0), "r"(a1), "r"(a2), "r"(a3), "r"(b0), "r"(b1));
}

__device__ __forceinline__ uint32_t smem_u32(const void* p) {
    uint32_t a;
    asm("{ .reg .u64 tmp; cvta.to.shared.u64 tmp, %1; cvt.u32.u64 %0, tmp; }"
        : "=r"(a) : "l"(p));
    return a;
}

__device__ __forceinline__ void cp16(uint32_t dst, const void* src) {
    asm volatile("cp.async.cg.shared.global [%0], [%1], 16;"
                 :: "r"(dst), "l"(src) : "memory");
}
#define CP_COMMIT() asm volatile("cp.async.commit_group;" ::: "memory")
#define CP_WAIT0()  asm volatile("cp.async.wait_group 0;" ::: "memory")
#define CP_WAIT2()  asm volatile("cp.async.wait_group 2;" ::: "memory")

// exp2 on the FMA pipe: degree-6 poly on f in [-0.5, 0.5], rel err ~1.2e-7.
__device__ __forceinline__ float exp2p(float x) {
    x = fmaxf(x, -126.0f);
    float n = rintf(x);
    float f = x - n;
    float p = 1.5403530e-4f;
    p = fmaf(p, f, 1.3333558e-3f);
    p = fmaf(p, f, 9.6181291e-3f);
    p = fmaf(p, f, 5.5504109e-2f);
    p = fmaf(p, f, 2.4022651e-1f);
    p = fmaf(p, f, 6.9314718e-1f);
    p = fmaf(p, f, 1.0f);
    float s = __int_as_float(((int)n + 127) << 23);
    return p * s;
}

// ============================================================================
// Pre-pass: tf32-round all three inputs in ONE launch (grid-stride, float4)
// ============================================================================
#define N4_X  ((B_*S_*E_) / 4)     // 1048576
#define N4_WQ ((3*E_*E_) / 4)      //  786432
#define N4_WP ((E_*E_) / 4)        //  262144
#define N4_ALL (N4_X + N4_WQ + N4_WP)

__global__ void round_all(const float4* __restrict__ x,
                          const float4* __restrict__ wq,
                          const float4* __restrict__ wp)
{
    int i = blockIdx.x * blockDim.x + threadIdx.x;
    const int stride = gridDim.x * blockDim.x;
    for (; i < N4_ALL; i += stride) {
        const float4* src;
        float4* dst;
        if (i < N4_X)            { src = x  + i;                 dst = (float4*)g_Xr + i; }
        else if (i < N4_X+N4_WQ) { src = wq + (i - N4_X);        dst = (float4*)g_Wq + (i - N4_X); }
        else                     { src = wp + (i - N4_X - N4_WQ); dst = (float4*)g_Wp + (i - N4_X - N4_WQ); }
        float4 v = *src;
        v.x = tf32_rna(v.x); v.y = tf32_rna(v.y);
        v.z = tf32_rna(v.z); v.w = tf32_rna(v.w);
        *dst = v;
    }
}

// ============================================================================
// TF32 warp-MMA GEMM (round-6 verified): CTA 128x64, 8 warps 4x2, warp 32x32,
// 4-stage cp.async, BK=16, 3 CTAs/SM.
// ============================================================================
#define KSTR 20
#define STGF (192*KSTR)
#define BROW (128*KSTR)
#define NSTG 4
#define GEMM_SMEM_BYTES (NSTG*STGF*4)   // 61440

__device__ __forceinline__ void gemm_fill(uint32_t smu, const float* __restrict__ Ab,
                                          const float* __restrict__ Bb,
                                          int stage, int chunk, int tid)
{
#pragma unroll
    for (int j = 0; j < 3; j++) {
        const int o = tid + 256 * j;
        const int r = o >> 2;
        const int q = (o & 3) * 4;
        const float* src;
        uint32_t off;
        if (r < 128) {
            src = Ab + (size_t)r * 1024 + chunk * 16 + q;
            off = (uint32_t)(stage * STGF + r * KSTR + q);
        } else {
            src = Bb + (size_t)(r - 128) * 1024 + chunk * 16 + q;
            off = (uint32_t)(stage * STGF + BROW + (r - 128) * KSTR + q);
        }
        cp16(smu + off * 4, src);
    }
}

__device__ __forceinline__ void gemm_tf32_pipe(const float* __restrict__ A,
                                               const float* __restrict__ Bm,
                                               int m0, int n0, float4 acc[2][4])
{
    extern __shared__ float sm[];
    const uint32_t smu = smem_u32(sm);
    const int tid  = threadIdx.x;
    const int lane = tid & 31;
    const int warp = tid >> 5;
    const int wm = (warp >> 1) * 32;
    const int wn = (warp & 1) * 32;
    const int g  = lane >> 2;
    const int t  = lane & 3;

    const float* Ab = A  + (size_t)m0 * 1024;
    const float* Bb = Bm + (size_t)n0 * 1024;

#pragma unroll
    for (int am = 0; am < 2; am++)
#pragma unroll
        for (int an = 0; an < 4; an++)
            acc[am][an] = make_float4(0.f, 0.f, 0.f, 0.f);

#pragma unroll
    for (int s = 0; s < NSTG - 1; s++) {
        gemm_fill(smu, Ab, Bb, s, s, tid);
        CP_COMMIT();
    }

    const int aOff = (wm + g) * KSTR + t;
    const int bOff = BROW + (wn + g) * KSTR + t;

    for (int c = 0; c < 64; ++c) {
        CP_WAIT2();
        __syncthreads();

        if (c + 3 < 64)
            gemm_fill(smu, Ab, Bb, (c + 3) & 3, c + 3, tid);
        CP_COMMIT();

        const float* st = sm + (c & 3) * STGF;

        uint32_t af[2][2][4], bf[2][4][2];
#pragma unroll
        for (int ks = 0; ks < 2; ++ks) {
#pragma unroll
            for (int am = 0; am < 2; am++) {
                const float* p = st + aOff + am * 16 * KSTR + ks * 8;
                af[ks][am][0] = __float_as_uint(p[0]);
                af[ks][am][1] = __float_as_uint(p[8 * KSTR]);
                af[ks][am][2] = __float_as_uint(p[4]);
                af[ks][am][3] = __float_as_uint(p[8 * KSTR + 4]);
            }
#pragma unroll
            for (int an = 0; an < 4; an++) {
                const float* p = st + bOff + an * 8 * KSTR + ks * 8;
                bf[ks][an][0] = __float_as_uint(p[0]);
                bf[ks][an][1] = __float_as_uint(p[4]);
            }
        }
#pragma unroll
        for (int ks = 0; ks < 2; ++ks)
#pragma unroll
            for (int am = 0; am < 2; am++)
#pragma unroll
                for (int an = 0; an < 4; an++)
                    mma_tf32(acc[am][an],
                             af[ks][am][0], af[ks][am][1], af[ks][am][2], af[ks][am][3],
                             bf[ks][an][0], bf[ks][an][1]);
    }
}

// ---------------------------------------------------------------------------
// Kernel 1: QKV GEMM. grid (48, 32).
// ---------------------------------------------------------------------------
#define QSCALE 0.18033688011112042f   // 0.125 * log2(e)

__global__ void __launch_bounds__(256, 3) qkv_mma()
{
    const int m0 = blockIdx.y * 128;
    const int n0 = blockIdx.x * 64;
    float4 acc[2][4];
    gemm_tf32_pipe(g_Xr, g_Wq, m0, n0, acc);

    const int lane = threadIdx.x & 31;
    const int warp = threadIdx.x >> 5;
    const int wm = (warp >> 1) * 32;
    const int wn = (warp & 1) * 32;
    const int g  = lane >> 2;
    const int t  = lane & 3;

#pragma unroll
    for (int an = 0; an < 4; an++) {
        const int ng  = n0 + wn + an * 8;        // n = h*192 + sel*64 + d
        const int grp = ng >> 6;
        const int h   = grp / 3;
        const int sel = grp - 3 * h;
        const int db  = (ng & 63) + t * 2;
        float* dst = (sel == 0) ? g_Q : ((sel == 1) ? g_K : g_V);
        const float sc = (sel == 0) ? QSCALE : 1.0f;
#pragma unroll
        for (int am = 0; am < 2; am++) {
#pragma unroll
            for (int half = 0; half < 2; half++) {
                const int m = m0 + wm + am * 16 + g + half * 8;
                const int b = m >> 11;
                const int s = m & 2047;
                float2 v;
                v.x = tf32_rna((half ? acc[am][an].z : acc[am][an].x) * sc);
                v.y = tf32_rna((half ? acc[am][an].w : acc[am][an].y) * sc);
                *(float2*)(dst + (((size_t)(b * 16 + h)) * 2048 + s) * 64 + db) = v;
            }
        }
    }
}

// ---------------------------------------------------------------------------
// Kernel 3: output projection. grid (16, 32).
// ---------------------------------------------------------------------------
__global__ void __launch_bounds__(256, 3) proj_mma(const float* __restrict__ bias,
                                                   float* __restrict__ out)
{
    const int m0 = blockIdx.y * 128;
    const int n0 = blockIdx.x * 64;
    float4 acc[2][4];
    gemm_tf32_pipe(g_O, g_Wp, m0, n0, acc);

    const int lane = threadIdx.x & 31;
    const int warp = threadIdx.x >> 5;
    const int wm = (warp >> 1) * 32;
    const int wn = (warp & 1) * 32;
    const int g  = lane >> 2;
    const int t  = lane & 3;

#pragma unroll
    for (int an = 0; an < 4; an++) {
        const int ng = n0 + wn + an * 8 + t * 2;
        const float2 bi = *(const float2*)(bias + ng);
#pragma unroll
        for (int am = 0; am < 2; am++) {
#pragma unroll
            for (int half = 0; half < 2; half++) {
                const int m = m0 + wm + am * 16 + g + half * 8;
                float2 v;
                v.x = (half ? acc[am][an].z : acc[am][an].x) + bi.x;
                v.y = (half ? acc[am][an].w : acc[am][an].y) + bi.y;
                *(float2*)(out + (size_t)m * 1024 + ng) = v;
            }
        }
    }
}

// ============================================================================
// Kernel 2: tensor-core causal flash attention.
// Round-4 verified structure; NOW 2 CTAs/SM (2x106496 B smem fits 228KB).
// ============================================================================
#define KSTRD 68
#define VSTRD 72
#define KBUF  (64*KSTRD)
#define OFF_V (2*KBUF)
#define VBUF  (64*VSTRD)
#define OFF_P (OFF_V + 2*VBUF)
#define FA_SMEM_BYTES ((OFF_P + 128*KSTRD) * 4)   // 106496

__global__ void __launch_bounds__(256, 2) flash_attn_tc()
{
    extern __shared__ float sm[];
    const uint32_t smu = smem_u32(sm);
    const int tid  = threadIdx.x;
    const int lane = tid & 31;
    const int warp = tid >> 5;
    const int g  = lane >> 2;
    const int t4 = lane & 3;
    const int qt = 15 - (int)blockIdx.x;
    const int bh = blockIdx.y;
    const int q0 = qt * 128;
    const int wr = warp * 16;
    const int tmax = 2 * qt + 1;

    const float* Qg = g_Q + (size_t)bh * S_ * 64;
    const float* Kg = g_K + (size_t)bh * S_ * 64;
    const float* Vg = g_V + (size_t)bh * S_ * 64;

    {
        const int r = tid >> 2;
        const int c = (tid & 3) * 16;
        const float* ks = Kg + (size_t)r * 64 + c;
        const float* vs = Vg + (size_t)r * 64 + c;
        const uint32_t kd = smu + (uint32_t)(r * KSTRD + c) * 4;
        const uint32_t vd = smu + (uint32_t)(OFF_V + r * VSTRD + c) * 4;
#pragma unroll
        for (int j = 0; j < 4; j++) {
            cp16(kd + j * 16, ks + j * 4);
            cp16(vd + j * 16, vs + j * 4);
        }
        CP_COMMIT();
    }

    {
        const int r  = tid >> 1;
        const int c0 = (tid & 1) * 32;
        const float* src = Qg + (size_t)(q0 + r) * 64 + c0;
        float* dst = sm + OFF_P + r * KSTRD + c0;
#pragma unroll
        for (int j = 0; j < 8; j++)
            *(float4*)(dst + j * 4) = *(const float4*)(src + j * 4);
    }
    __syncthreads();

    uint32_t qf[8][4];
#pragma unroll
    for (int kk = 0; kk < 8; kk++) {
        const float* p = sm + OFF_P + (wr + g) * KSTRD + kk * 8 + t4;
        qf[kk][0] = __float_as_uint(p[0]);
        qf[kk][1] = __float_as_uint(p[8 * KSTRD]);
        qf[kk][2] = __float_as_uint(p[4]);
        qf[kk][3] = __float_as_uint(p[8 * KSTRD + 4]);
    }

    float m2[2] = {-1e30f, -1e30f};
    float l2[2] = {0.f, 0.f};
    float4 of[8];
#pragma unroll
    for (int an = 0; an < 8; an++) of[an] = make_float4(0.f, 0.f, 0.f, 0.f);

    for (int t = 0; t <= tmax; t++) {
        CP_WAIT0();
        __syncthreads();

        if (t < tmax) {
            const int kv1 = (t + 1) * 64;
            const int buf = (t + 1) & 1;
            const int r = tid >> 2;
            const int c = (tid & 3) * 16;
            const float* ks = Kg + (size_t)(kv1 + r) * 64 + c;
            const float* vs = Vg + (size_t)(kv1 + r) * 64 + c;
            const uint32_t kd = smu + (uint32_t)(buf * KBUF + r * KSTRD + c) * 4;
            const uint32_t vd = smu + (uint32_t)(OFF_V + buf * VBUF + r * VSTRD + c) * 4;
#pragma unroll
            for (int j = 0; j < 4; j++) {
                cp16(kd + j * 16, ks + j * 4);
                cp16(vd + j * 16, vs + j * 4);
            }
            CP_COMMIT();
        }

        const int kv0 = t * 64;
        if (kv0 <= q0 + wr + 15) {
            const float* smK = sm + (t & 1) * KBUF;
            const float* smV = sm + OFF_V + (t & 1) * VBUF;

            float4 sf[8];
#pragma unroll
            for (int an = 0; an < 8; an++) sf[an] = make_float4(0.f, 0.f, 0.f, 0.f);
#pragma unroll
            for (int kk = 0; kk < 8; kk++) {
#pragma unroll
                for (int an = 0; an < 8; an++) {
                    const float* bp = smK + (an * 8 + g) * KSTRD + kk * 8 + t4;
                    mma_tf32(sf[an], qf[kk][0], qf[kk][1], qf[kk][2], qf[kk][3],
                             __float_as_uint(bp[0]), __float_as_uint(bp[4]));
                }
            }

            if (kv0 + 63 > q0 + wr) {
                const int r0 = q0 + wr + g;
                const int r1 = r0 + 8;
#pragma unroll
                for (int an = 0; an < 8; an++) {
                    const int col = kv0 + an * 8 + 2 * t4;
                    if (col     > r0) sf[an].x = -1e30f;
                    if (col + 1 > r0) sf[an].y = -1e30f;
                    if (col     > r1) sf[an].z = -1e30f;
                    if (col + 1 > r1) sf[an].w = -1e30f;
                }
            }

            float mt0 = -1e30f, mt1 = -1e30f;
#pragma unroll
            for (int an = 0; an < 8; an++) {
                mt0 = fmaxf(mt0, fmaxf(sf[an].x, sf[an].y));
                mt1 = fmaxf(mt1, fmaxf(sf[an].z, sf[an].w));
            }
            mt0 = fmaxf(mt0, __shfl_xor_sync(0xffffffffu, mt0, 1));
            mt0 = fmaxf(mt0, __shfl_xor_sync(0xffffffffu, mt0, 2));
            mt1 = fmaxf(mt1, __shfl_xor_sync(0xffffffffu, mt1, 1));
            mt1 = fmaxf(mt1, __shfl_xor_sync(0xffffffffu, mt1, 2));

            const float mn0 = fmaxf(m2[0], mt0);
            const float mn1 = fmaxf(m2[1], mt1);
            const float a0 = exp2p(m2[0] - mn0);
            const float a1 = exp2p(m2[1] - mn1);
            m2[0] = mn0; m2[1] = mn1;

            float s0 = 0.f, s1 = 0.f;
#pragma unroll
            for (int an = 0; an < 8; an++) {
                sf[an].x = tf32_rna(exp2p(sf[an].x - mn0));
                sf[an].y = tf32_rna(exp2p(sf[an].y - mn0));
                sf[an].z = tf32_rna(exp2p(sf[an].z - mn1));
                sf[an].w = tf32_rna(exp2p(sf[an].w - mn1));
                s0 += sf[an].x + sf[an].y;
                s1 += sf[an].z + sf[an].w;
            }
            s0 += __shfl_xor_sync(0xffffffffu, s0, 1);
            s0 += __shfl_xor_sync(0xffffffffu, s0, 2);
            s1 += __shfl_xor_sync(0xffffffffu, s1, 1);
            s1 += __shfl_xor_sync(0xffffffffu, s1, 2);
            l2[0] = l2[0] * a0 + s0;
            l2[1] = l2[1] * a1 + s1;

#pragma unroll
            for (int an = 0; an < 8; an++) {
                of[an].x *= a0; of[an].y *= a0;
                of[an].z *= a1; of[an].w *= a1;
            }

            {
                float* pp = sm + OFF_P + (wr + g) * KSTRD;
#pragma unroll
                for (int an = 0; an < 8; an++) {
                    *(float2*)(pp + an * 8 + 2 * t4) = make_float2(sf[an].x, sf[an].y);
                    *(float2*)(pp + 8 * KSTRD + an * 8 + 2 * t4) = make_float2(sf[an].z, sf[an].w);
                }
            }
            __syncwarp();

#pragma unroll
            for (int kk = 0; kk < 8; kk++) {
                const float* ap = sm + OFF_P + (wr + g) * KSTRD + kk * 8 + t4;
                const uint32_t A0 = __float_as_uint(ap[0]);
                const uint32_t A1 = __float_as_uint(ap[8 * KSTRD]);
                const uint32_t A2 = __float_as_uint(ap[4]);
                const uint32_t A3 = __float_as_uint(ap[8 * KSTRD + 4]);
#pragma unroll
                for (int an = 0; an < 8; an++) {
                    const float* vp = smV + (kk * 8 + t4) * VSTRD + an * 8 + g;
                    mma_tf32(of[an], A0, A1, A2, A3,
                             __float_as_uint(vp[0]), __float_as_uint(vp[4 * VSTRD]));
                }
            }
        }
        __syncthreads();
    }

    const int b = bh >> 4;
    const int h = bh & 15;
    const float i0 = 1.0f / l2[0];
    const float i1 = 1.0f / l2[1];
    const int r0 = q0 + wr + g;
    const int r1 = r0 + 8;
    float* o0 = g_O + ((size_t)b * 2048 + r0) * 1024 + h * 64;
    float* o1 = g_O + ((size_t)b * 2048 + r1) * 1024 + h * 64;
#pragma unroll
    for (int an = 0; an < 8; an++) {
        const int d = an * 8 + 2 * t4;
        *(float2*)(o0 + d) = make_float2(tf32_rna(of[an].x * i0), tf32_rna(of[an].y * i0));
        *(float2*)(o1 + d) = make_float2(tf32_rna(of[an].z * i1), tf32_rna(of[an].w * i1));
    }
}

// ---------------------------------------------------------------------------
extern "C" void kernel_launch(void* const* d_in, const int* in_sizes, int n_in,
                              void* d_out, int out_size)
{
    const float* x      = (const float*)d_in[0];  // (2,2048,1024)
    const float* w_qkv  = (const float*)d_in[1];  // (3072,1024)
    const float* w_proj = (const float*)d_in[2];  // (1024,1024)
    const float* b_proj = (const float*)d_in[3];  // (1024,)
    float* out = (float*)d_out;

    cudaFuncSetAttribute(flash_attn_tc, cudaFuncAttributeMaxDynamicSharedMemorySize,
                         FA_SMEM_BYTES);
    cudaFuncSetAttribute(qkv_mma, cudaFuncAttributeMaxDynamicSharedMemorySize,
                         GEMM_SMEM_BYTES);
    cudaFuncSetAttribute(proj_mma, cudaFuncAttributeMaxDynamicSharedMemorySize,
                         GEMM_SMEM_BYTES);

    round_all<<<592, 256>>>((const float4*)x, (const float4*)w_qkv,
                            (const float4*)w_proj);

    qkv_mma<<<dim3(48, 32), 256, GEMM_SMEM_BYTES>>>();
    flash_attn_tc<<<dim3(16, 32), 256, FA_SMEM_BYTES>>>();
    proj_mma<<<dim3(16, 32), 256, GEMM_SMEM_BYTES>>>(b_proj, out);
}

// round 8
// speedup vs baseline: 1.1286x; 1.1286x over previous
#include <cuda_runtime.h>
#include <math.h>
#include <stdint.h>

#define B_  2
#define S_  2048
#define E_  1024
#define H_  16
#define HD_ 64

// Scratch (allocation-free: __device__ globals)
__device__ float g_Q[B_*H_*S_*HD_];   // tf32-rounded, pre-scaled by 0.125*log2(e)
__device__ float g_K[B_*H_*S_*HD_];   // tf32-rounded
__device__ float g_V[B_*H_*S_*HD_];   // tf32-rounded
__device__ float g_O[B_*S_*E_];       // attention out, tf32-rounded (proj A input)
__device__ float g_Xr[B_*S_*E_];      // tf32-rounded x, k-chunk permuted
__device__ float g_Wq[3*E_*E_];       // tf32-rounded w_qkv, k-chunk permuted
__device__ float g_Wp[E_*E_];         // tf32-rounded w_proj, k-chunk permuted

// ============================================================================
// PTX helpers (plain sm_80+ ISA — no 'a'-suffix features)
// ============================================================================
__device__ __forceinline__ float tf32_rna(float x) {
    uint32_t r;
    asm("cvt.rna.tf32.f32 %0, %1;" : "=r"(r) : "f"(x));
    return __uint_as_float(r);
}

__device__ __forceinline__ void mma_tf32(float4& d,
                                         uint32_t a0, uint32_t a1, uint32_t a2, uint32_t a3,
                                         uint32_t b0, uint32_t b1)
{
    asm volatile(
        "mma.sync.aligned.m16n8k8.row.col.f32.tf32.tf32.f32 "
        "{%0,%1,%2,%3}, {%4,%5,%6,%7}, {%8,%9}, {%0,%1,%2,%3};"
        : "+f"(d.x), "+f"(d.y), "+f"(d.z), "+f"(d.w)
        : "r"(a0), "r"(a1), "r"(a2), "r"(a3), "r"(b0), "r"(b1));
}

__device__ __forceinline__ uint32_t smem_u32(const void* p) {
    uint32_t a;
    asm("{ .reg .u64 tmp; cvta.to.shared.u64 tmp, %1; cvt.u32.u64 %0, tmp; }"
        : "=r"(a) : "l"(p));
    return a;
}

__device__ __forceinline__ void cp16(uint32_t dst, const void* src) {
    asm volatile("cp.async.cg.shared.global [%0], [%1], 16;"
                 :: "r"(dst), "l"(src) : "memory");
}
#define CP_COMMIT() asm volatile("cp.async.commit_group;" ::: "memory")
#define CP_WAIT0()  asm volatile("cp.async.wait_group 0;" ::: "memory")
#define CP_WAIT2()  asm volatile("cp.async.wait_group 2;" ::: "memory")

// exp2 on the FMA pipe: degree-6 poly on f in [-0.5, 0.5], rel err ~1.2e-7.
__device__ __forceinline__ float exp2p(float x) {
    x = fmaxf(x, -126.0f);
    float n = rintf(x);
    float f = x - n;
    float p = 1.5403530e-4f;
    p = fmaf(p, f, 1.3333558e-3f);
    p = fmaf(p, f, 9.6181291e-3f);
    p = fmaf(p, f, 5.5504109e-2f);
    p = fmaf(p, f, 2.4022651e-1f);
    p = fmaf(p, f, 6.9314718e-1f);
    p = fmaf(p, f, 1.0f);
    float s = __int_as_float(((int)n + 127) << 23);
    return p * s;
}

// ============================================================================
// Pre-pass: tf32-round AND k-chunk-permute all three GEMM inputs.
// Permutation per 16-float block: output position 4t+{0,1,2,3} holds original
// columns {t, t+4, t+8, t+12} (self-inverse pi(c) = (c%4)*4 + c/4).
// ============================================================================
#define N4_X  ((B_*S_*E_) / 4)
#define N4_WQ ((3*E_*E_) / 4)
#define N4_WP ((E_*E_) / 4)
#define N4_ALL (N4_X + N4_WQ + N4_WP)

__global__ void round_perm_all(const float* __restrict__ x,
                               const float* __restrict__ wq,
                               const float* __restrict__ wp)
{
    int f = blockIdx.x * blockDim.x + threadIdx.x;   // output float4 index
    const int stride = gridDim.x * blockDim.x;
    for (; f < N4_ALL; f += stride) {
        const float* s;
        float4* d;
        int i = f;
        if (i < N4_X)               { s = x;  d = (float4*)g_Xr; }
        else if (i < N4_X + N4_WQ)  { i -= N4_X;         s = wq; d = (float4*)g_Wq; }
        else                        { i -= N4_X + N4_WQ; s = wp; d = (float4*)g_Wp; }
        const int t    = i & 3;
        const int base = (i >> 2) << 4;   // float offset of the 16-block
        float4 v;
        v.x = tf32_rna(s[base + t]);
        v.y = tf32_rna(s[base + t + 4]);
        v.z = tf32_rna(s[base + t + 8]);
        v.w = tf32_rna(s[base + t + 12]);
        d[i] = v;
    }
}

// ============================================================================
// TF32 warp-MMA GEMM: CTA 128x64, 8 warps 4x2, warp 32x32, 4-stage cp.async,
// BK=16, 3 CTAs/SM.
// APERM=true : A is k-chunk permuted -> A+B fragments via 8x LDS.128/chunk.
// APERM=false: A normal (scalar frag loads, stride 20); B still vectorized.
// ============================================================================
template<bool APERM> struct GeoT;
template<> struct GeoT<true>  { static const int ASTR = 16; };
template<> struct GeoT<false> { static const int ASTR = 20; };

#define NSTG 4

template<bool APERM>
__device__ __forceinline__ void gemm_fill(uint32_t smu, const float* __restrict__ Ab,
                                          const float* __restrict__ Bb,
                                          int stage, int chunk, int tid)
{
    const int ASTR = GeoT<APERM>::ASTR;
    const int BROW = 128 * ASTR;
    const int STGF = BROW + 64 * 16;
#pragma unroll
    for (int j = 0; j < 3; j++) {
        const int o = tid + 256 * j;      // 0..767
        const int r = o >> 2;             // 0..191
        const int q = (o & 3) * 4;
        const float* src;
        uint32_t off;
        if (r < 128) {
            src = Ab + (size_t)r * 1024 + chunk * 16 + q;
            off = (uint32_t)(stage * STGF + r * ASTR + q);
        } else {
            src = Bb + (size_t)(r - 128) * 1024 + chunk * 16 + q;
            off = (uint32_t)(stage * STGF + BROW + (r - 128) * 16 + q);
        }
        cp16(smu + off * 4, src);
    }
}

template<bool APERM>
__device__ __forceinline__ void gemm_tf32_pipe(const float* __restrict__ A,
                                               const float* __restrict__ Bm,
                                               int m0, int n0, float4 acc[2][4])
{
    const int ASTR = GeoT<APERM>::ASTR;
    const int BROW = 128 * ASTR;
    const int STGF = BROW + 64 * 16;

    extern __shared__ float sm[];
    const uint32_t smu = smem_u32(sm);
    const int tid  = threadIdx.x;
    const int lane = tid & 31;
    const int warp = tid >> 5;
    const int wm = (warp >> 1) * 32;
    const int wn = (warp & 1) * 32;
    const int g  = lane >> 2;
    const int t  = lane & 3;

    const float* Ab = A  + (size_t)m0 * 1024;
    const float* Bb = Bm + (size_t)n0 * 1024;

#pragma unroll
    for (int am = 0; am < 2; am++)
#pragma unroll
        for (int an = 0; an < 4; an++)
            acc[am][an] = make_float4(0.f, 0.f, 0.f, 0.f);

#pragma unroll
    for (int s = 0; s < NSTG - 1; s++) {
        gemm_fill<APERM>(smu, Ab, Bb, s, s, tid);
        CP_COMMIT();
    }

    for (int c = 0; c < 64; ++c) {
        CP_WAIT2();
        __syncthreads();

        if (c + 3 < 64)
            gemm_fill<APERM>(smu, Ab, Bb, (c + 3) & 3, c + 3, tid);
        CP_COMMIT();

        const float* st = sm + (c & 3) * STGF;

        // ---- B fragments: 4x LDS.128 (permuted layout) ----
        float4 vb[4];
#pragma unroll
        for (int an = 0; an < 4; an++)
            vb[an] = *(const float4*)(st + BROW + (wn + an * 8 + g) * 16 + 4 * t);

        if (APERM) {
            // ---- A fragments: 4x LDS.128 ----
            float4 vaL[2], vaH[2];
#pragma unroll
            for (int am = 0; am < 2; am++) {
                vaL[am] = *(const float4*)(st + (wm + am * 16 + g)     * 16 + 4 * t);
                vaH[am] = *(const float4*)(st + (wm + am * 16 + g + 8) * 16 + 4 * t);
            }
#pragma unroll
            for (int am = 0; am < 2; am++)
#pragma unroll
                for (int an = 0; an < 4; an++) {
                    mma_tf32(acc[am][an],
                             __float_as_uint(vaL[am].x), __float_as_uint(vaH[am].x),
                             __float_as_uint(vaL[am].y), __float_as_uint(vaH[am].y),
                             __float_as_uint(vb[an].x),  __float_as_uint(vb[an].y));
                    mma_tf32(acc[am][an],
                             __float_as_uint(vaL[am].z), __float_as_uint(vaH[am].z),
                             __float_as_uint(vaL[am].w), __float_as_uint(vaH[am].w),
                             __float_as_uint(vb[an].z),  __float_as_uint(vb[an].w));
                }
        } else {
            // ---- A fragments: scalar loads (unpermuted), stride 20 ----
            uint32_t af[2][2][4];
#pragma unroll
            for (int ks = 0; ks < 2; ++ks)
#pragma unroll
                for (int am = 0; am < 2; am++) {
                    const float* p = st + (wm + am * 16 + g) * ASTR + ks * 8 + t;
                    af[ks][am][0] = __float_as_uint(p[0]);
                    af[ks][am][1] = __float_as_uint(p[8 * ASTR]);
                    af[ks][am][2] = __float_as_uint(p[4]);
                    af[ks][am][3] = __float_as_uint(p[8 * ASTR + 4]);
                }
#pragma unroll
            for (int am = 0; am < 2; am++)
#pragma unroll
                for (int an = 0; an < 4; an++) {
                    mma_tf32(acc[am][an],
                             af[0][am][0], af[0][am][1], af[0][am][2], af[0][am][3],
                             __float_as_uint(vb[an].x), __float_as_uint(vb[an].y));
                    mma_tf32(acc[am][an],
                             af[1][am][0], af[1][am][1], af[1][am][2], af[1][am][3],
                             __float_as_uint(vb[an].z), __float_as_uint(vb[an].w));
                }
        }
    }
}

#define QKV_SMEM_BYTES  (NSTG * (128*16 + 64*16) * 4)   // 49152
#define PROJ_SMEM_BYTES (NSTG * (128*20 + 64*16) * 4)   // 57344

// ---------------------------------------------------------------------------
// Kernel 1: QKV GEMM. grid (48, 32).
// ---------------------------------------------------------------------------
#define QSCALE 0.18033688011112042f   // 0.125 * log2(e)

__global__ void __launch_bounds__(256, 3) qkv_mma()
{
    const int m0 = blockIdx.y * 128;
    const int n0 = blockIdx.x * 64;
    float4 acc[2][4];
    gemm_tf32_pipe<true>(g_Xr, g_Wq, m0, n0, acc);

    const int lane = threadIdx.x & 31;
    const int warp = threadIdx.x >> 5;
    const int wm = (warp >> 1) * 32;
    const int wn = (warp & 1) * 32;
    const int g  = lane >> 2;
    const int t  = lane & 3;

#pragma unroll
    for (int an = 0; an < 4; an++) {
        const int ng  = n0 + wn + an * 8;        // n = h*192 + sel*64 + d
        const int grp = ng >> 6;
        const int h   = grp / 3;
        const int sel = grp - 3 * h;
        const int db  = (ng & 63) + t * 2;
        float* dst = (sel == 0) ? g_Q : ((sel == 1) ? g_K : g_V);
        const float sc = (sel == 0) ? QSCALE : 1.0f;
#pragma unroll
        for (int am = 0; am < 2; am++) {
#pragma unroll
            for (int half = 0; half < 2; half++) {
                const int m = m0 + wm + am * 16 + g + half * 8;
                const int b = m >> 11;
                const int s = m & 2047;
                float2 v;
                v.x = tf32_rna((half ? acc[am][an].z : acc[am][an].x) * sc);
                v.y = tf32_rna((half ? acc[am][an].w : acc[am][an].y) * sc);
                *(float2*)(dst + (((size_t)(b * 16 + h)) * 2048 + s) * 64 + db) = v;
            }
        }
    }
}

// ---------------------------------------------------------------------------
// Kernel 3: output projection. grid (16, 32). A = g_O (unpermuted).
// ---------------------------------------------------------------------------
__global__ void __launch_bounds__(256, 3) proj_mma(const float* __restrict__ bias,
                                                   float* __restrict__ out)
{
    const int m0 = blockIdx.y * 128;
    const int n0 = blockIdx.x * 64;
    float4 acc[2][4];
    gemm_tf32_pipe<false>(g_O, g_Wp, m0, n0, acc);

    const int lane = threadIdx.x & 31;
    const int warp = threadIdx.x >> 5;
    const int wm = (warp >> 1) * 32;
    const int wn = (warp & 1) * 32;
    const int g  = lane >> 2;
    const int t  = lane & 3;

#pragma unroll
    for (int an = 0; an < 4; an++) {
        const int ng = n0 + wn + an * 8 + t * 2;
        const float2 bi = *(const float2*)(bias + ng);
#pragma unroll
        for (int am = 0; am < 2; am++) {
#pragma unroll
            for (int half = 0; half < 2; half++) {
                const int m = m0 + wm + am * 16 + g + half * 8;
                float2 v;
                v.x = (half ? acc[am][an].z : acc[am][an].x) + bi.x;
                v.y = (half ? acc[am][an].w : acc[am][an].y) + bi.y;
                *(float2*)(out + (size_t)m * 1024 + ng) = v;
            }
        }
    }
}

// ============================================================================
// Kernel 2: tensor-core causal flash attention (round-6 verified config:
// 1 CTA/SM — (256,2) regressed in round 7 via register spills).
// ============================================================================
#define KSTRD 68
#define VSTRD 72
#define KBUF  (64*KSTRD)
#define OFF_V (2*KBUF)
#define VBUF  (64*VSTRD)
#define OFF_P (OFF_V + 2*VBUF)
#define FA_SMEM_BYTES ((OFF_P + 128*KSTRD) * 4)   // 106496

__global__ void __launch_bounds__(256, 1) flash_attn_tc()
{
    extern __shared__ float sm[];
    const uint32_t smu = smem_u32(sm);
    const int tid  = threadIdx.x;
    const int lane = tid & 31;
    const int warp = tid >> 5;
    const int g  = lane >> 2;
    const int t4 = lane & 3;
    const int qt = 15 - (int)blockIdx.x;
    const int bh = blockIdx.y;
    const int q0 = qt * 128;
    const int wr = warp * 16;
    const int tmax = 2 * qt + 1;

    const float* Qg = g_Q + (size_t)bh * S_ * 64;
    const float* Kg = g_K + (size_t)bh * S_ * 64;
    const float* Vg = g_V + (size_t)bh * S_ * 64;

    {
        const int r = tid >> 2;
        const int c = (tid & 3) * 16;
        const float* ks = Kg + (size_t)r * 64 + c;
        const float* vs = Vg + (size_t)r * 64 + c;
        const uint32_t kd = smu + (uint32_t)(r * KSTRD + c) * 4;
        const uint32_t vd = smu + (uint32_t)(OFF_V + r * VSTRD + c) * 4;
#pragma unroll
        for (int j = 0; j < 4; j++) {
            cp16(kd + j * 16, ks + j * 4);
            cp16(vd + j * 16, vs + j * 4);
        }
        CP_COMMIT();
    }

    {
        const int r  = tid >> 1;
        const int c0 = (tid & 1) * 32;
        const float* src = Qg + (size_t)(q0 + r) * 64 + c0;
        float* dst = sm + OFF_P + r * KSTRD + c0;
#pragma unroll
        for (int j = 0; j < 8; j++)
            *(float4*)(dst + j * 4) = *(const float4*)(src + j * 4);
    }
    __syncthreads();

    uint32_t qf[8][4];
#pragma unroll
    for (int kk = 0; kk < 8; kk++) {
        const float* p = sm + OFF_P + (wr + g) * KSTRD + kk * 8 + t4;
        qf[kk][0] = __float_as_uint(p[0]);
        qf[kk][1] = __float_as_uint(p[8 * KSTRD]);
        qf[kk][2] = __float_as_uint(p[4]);
        qf[kk][3] = __float_as_uint(p[8 * KSTRD + 4]);
    }

    float m2[2] = {-1e30f, -1e30f};
    float l2[2] = {0.f, 0.f};
    float4 of[8];
#pragma unroll
    for (int an = 0; an < 8; an++) of[an] = make_float4(0.f, 0.f, 0.f, 0.f);

    for (int t = 0; t <= tmax; t++) {
        CP_WAIT0();
        __syncthreads();

        if (t < tmax) {
            const int kv1 = (t + 1) * 64;
            const int buf = (t + 1) & 1;
            const int r = tid >> 2;
            const int c = (tid & 3) * 16;
            const float* ks = Kg + (size_t)(kv1 + r) * 64 + c;
            const float* vs = Vg + (size_t)(kv1 + r) * 64 + c;
            const uint32_t kd = smu + (uint32_t)(buf * KBUF + r * KSTRD + c) * 4;
            const uint32_t vd = smu + (uint32_t)(OFF_V + buf * VBUF + r * VSTRD + c) * 4;
#pragma unroll
            for (int j = 0; j < 4; j++) {
                cp16(kd + j * 16, ks + j * 4);
                cp16(vd + j * 16, vs + j * 4);
            }
            CP_COMMIT();
        }

        const int kv0 = t * 64;
        if (kv0 <= q0 + wr + 15) {
            const float* smK = sm + (t & 1) * KBUF;
            const float* smV = sm + OFF_V + (t & 1) * VBUF;

            float4 sf[8];
#pragma unroll
            for (int an = 0; an < 8; an++) sf[an] = make_float4(0.f, 0.f, 0.f, 0.f);
#pragma unroll
            for (int kk = 0; kk < 8; kk++) {
#pragma unroll
                for (int an = 0; an < 8; an++) {
                    const float* bp = smK + (an * 8 + g) * KSTRD + kk * 8 + t4;
                    mma_tf32(sf[an], qf[kk][0], qf[kk][1], qf[kk][2], qf[kk][3],
                             __float_as_uint(bp[0]), __float_as_uint(bp[4]));
                }
            }

            if (kv0 + 63 > q0 + wr) {
                const int r0 = q0 + wr + g;
                const int r1 = r0 + 8;
#pragma unroll
                for (int an = 0; an < 8; an++) {
                    const int col = kv0 + an * 8 + 2 * t4;
                    if (col     > r0) sf[an].x = -1e30f;
                    if (col + 1 > r0) sf[an].y = -1e30f;
                    if (col     > r1) sf[an].z = -1e30f;
                    if (col + 1 > r1) sf[an].w = -1e30f;
                }
            }

            float mt0 = -1e30f, mt1 = -1e30f;
#pragma unroll
            for (int an = 0; an < 8; an++) {
                mt0 = fmaxf(mt0, fmaxf(sf[an].x, sf[an].y));
                mt1 = fmaxf(mt1, fmaxf(sf[an].z, sf[an].w));
            }
            mt0 = fmaxf(mt0, __shfl_xor_sync(0xffffffffu, mt0, 1));
            mt0 = fmaxf(mt0, __shfl_xor_sync(0xffffffffu, mt0, 2));
            mt1 = fmaxf(mt1, __shfl_xor_sync(0xffffffffu, mt1, 1));
            mt1 = fmaxf(mt1, __shfl_xor_sync(0xffffffffu, mt1, 2));

            const float mn0 = fmaxf(m2[0], mt0);
            const float mn1 = fmaxf(m2[1], mt1);
            const float a0 = exp2p(m2[0] - mn0);
            const float a1 = exp2p(m2[1] - mn1);
            m2[0] = mn0; m2[1] = mn1;

            float s0 = 0.f, s1 = 0.f;
#pragma unroll
            for (int an = 0; an < 8; an++) {
                sf[an].x = tf32_rna(exp2p(sf[an].x - mn0));
                sf[an].y = tf32_rna(exp2p(sf[an].y - mn0));
                sf[an].z = tf32_rna(exp2p(sf[an].z - mn1));
                sf[an].w = tf32_rna(exp2p(sf[an].w - mn1));
                s0 += sf[an].x + sf[an].y;
                s1 += sf[an].z + sf[an].w;
            }
            s0 += __shfl_xor_sync(0xffffffffu, s0, 1);
            s0 += __shfl_xor_sync(0xffffffffu, s0, 2);
            s1 += __shfl_xor_sync(0xffffffffu, s1, 1);
            s1 += __shfl_xor_sync(0xffffffffu, s1, 2);
            l2[0] = l2[0] * a0 + s0;
            l2[1] = l2[1] * a1 + s1;

#pragma unroll
            for (int an = 0; an < 8; an++) {
                of[an].x *= a0; of[an].y *= a0;
                of[an].z *= a1; of[an].w *= a1;
            }

            {
                float* pp = sm + OFF_P + (wr + g) * KSTRD;
#pragma unroll
                for (int an = 0; an < 8; an++) {
                    *(float2*)(pp + an * 8 + 2 * t4) = make_float2(sf[an].x, sf[an].y);
                    *(float2*)(pp + 8 * KSTRD + an * 8 + 2 * t4) = make_float2(sf[an].z, sf[an].w);
                }
            }
            __syncwarp();

#pragma unroll
            for (int kk = 0; kk < 8; kk++) {
                const float* ap = sm + OFF_P + (wr + g) * KSTRD + kk * 8 + t4;
                const uint32_t A0 = __float_as_uint(ap[0]);
                const uint32_t A1 = __float_as_uint(ap[8 * KSTRD]);
                const uint32_t A2 = __float_as_uint(ap[4]);
                const uint32_t A3 = __float_as_uint(ap[8 * KSTRD + 4]);
#pragma unroll
                for (int an = 0; an < 8; an++) {
                    const float* vp = smV + (kk * 8 + t4) * VSTRD + an * 8 + g;
                    mma_tf32(of[an], A0, A1, A2, A3,
                             __float_as_uint(vp[0]), __float_as_uint(vp[4 * VSTRD]));
                }
            }
        }
        __syncthreads();
    }

    const int b = bh >> 4;
    const int h = bh & 15;
    const float i0 = 1.0f / l2[0];
    const float i1 = 1.0f / l2[1];
    const int r0 = q0 + wr + g;
    const int r1 = r0 + 8;
    float* o0 = g_O + ((size_t)b * 2048 + r0) * 1024 + h * 64;
    float* o1 = g_O + ((size_t)b * 2048 + r1) * 1024 + h * 64;
#pragma unroll
    for (int an = 0; an < 8; an++) {
        const int d = an * 8 + 2 * t4;
        *(float2*)(o0 + d) = make_float2(tf32_rna(of[an].x * i0), tf32_rna(of[an].y * i0));
        *(float2*)(o1 + d) = make_float2(tf32_rna(of[an].z * i1), tf32_rna(of[an].w * i1));
    }
}

// ---------------------------------------------------------------------------
extern "C" void kernel_launch(void* const* d_in, const int* in_sizes, int n_in,
                              void* d_out, int out_size)
{
    const float* x      = (const float*)d_in[0];  // (2,2048,1024)
    const float* w_qkv  = (const float*)d_in[1];  // (3072,1024)
    const float* w_proj = (const float*)d_in[2];  // (1024,1024)
    const float* b_proj = (const float*)d_in[3];  // (1024,)
    float* out = (float*)d_out;

    cudaFuncSetAttribute(flash_attn_tc, cudaFuncAttributeMaxDynamicSharedMemorySize,
                         FA_SMEM_BYTES);
    cudaFuncSetAttribute(qkv_mma, cudaFuncAttributeMaxDynamicSharedMemorySize,
                         QKV_SMEM_BYTES);
    cudaFuncSetAttribute(proj_mma, cudaFuncAttributeMaxDynamicSharedMemorySize,
                         PROJ_SMEM_BYTES);

    round_perm_all<<<592, 256>>>(x, w_qkv, w_proj);

    qkv_mma<<<dim3(48, 32), 256, QKV_SMEM_BYTES>>>();
    flash_attn_tc<<<dim3(16, 32), 256, FA_SMEM_BYTES>>>();
    proj_mma<<<dim3(16, 32), 256, PROJ_SMEM_BYTES>>>(b_proj, out);
}

// round 9
// speedup vs baseline: 1.1332x; 1.0040x over previous
#include <cuda_runtime.h>
#include <math.h>
#include <stdint.h>

#define B_  2
#define S_  2048
#define E_  1024
#define H_  16
#define HD_ 64

// Scratch (allocation-free: __device__ globals)
__device__ float g_Q[B_*H_*S_*HD_];   // (b,h,s,d) tf32-rounded, scaled 0.125*log2(e)
__device__ float g_K[B_*H_*S_*HD_];   // (b,h,s,d) tf32-rounded, d 16-block-permuted
__device__ float g_V[B_*H_*S_*HD_];   // (b,h,d,s) TRANSPOSED, s 16-block-permuted
__device__ float g_O[B_*S_*E_];       // attention out, tf32-rounded (proj A input)
__device__ float g_Xr[B_*S_*E_];      // tf32-rounded x, k-chunk permuted
__device__ float g_Wq[3*E_*E_];       // tf32-rounded w_qkv, k-chunk permuted
__device__ float g_Wp[E_*E_];         // tf32-rounded w_proj, k-chunk permuted

// ============================================================================
// PTX helpers (plain sm_80+ ISA)
// ============================================================================
__device__ __forceinline__ float tf32_rna(float x) {
    uint32_t r;
    asm("cvt.rna.tf32.f32 %0, %1;" : "=r"(r) : "f"(x));
    return __uint_as_float(r);
}

__device__ __forceinline__ void mma_tf32(float4& d,
                                         uint32_t a0, uint32_t a1, uint32_t a2, uint32_t a3,
                                         uint32_t b0, uint32_t b1)
{
    asm volatile(
        "mma.sync.aligned.m16n8k8.row.col.f32.tf32.tf32.f32 "
        "{%0,%1,%2,%3}, {%4,%5,%6,%7}, {%8,%9}, {%0,%1,%2,%3};"
        : "+f"(d.x), "+f"(d.y), "+f"(d.z), "+f"(d.w)
        : "r"(a0), "r"(a1), "r"(a2), "r"(a3), "r"(b0), "r"(b1));
}

__device__ __forceinline__ uint32_t smem_u32(const void* p) {
    uint32_t a;
    asm("{ .reg .u64 tmp; cvta.to.shared.u64 tmp, %1; cvt.u32.u64 %0, tmp; }"
        : "=r"(a) : "l"(p));
    return a;
}

__device__ __forceinline__ void cp16(uint32_t dst, const void* src) {
    asm volatile("cp.async.cg.shared.global [%0], [%1], 16;"
                 :: "r"(dst), "l"(src) : "memory");
}
#define CP_COMMIT() asm volatile("cp.async.commit_group;" ::: "memory")
#define CP_WAIT0()  asm volatile("cp.async.wait_group 0;" ::: "memory")
#define CP_WAIT2()  asm volatile("cp.async.wait_group 2;" ::: "memory")

// exp2 on the FMA pipe: degree-6 poly on f in [-0.5, 0.5], rel err ~1.2e-7.
__device__ __forceinline__ float exp2p(float x) {
    x = fmaxf(x, -126.0f);
    float n = rintf(x);
    float f = x - n;
    float p = 1.5403530e-4f;
    p = fmaf(p, f, 1.3333558e-3f);
    p = fmaf(p, f, 9.6181291e-3f);
    p = fmaf(p, f, 5.5504109e-2f);
    p = fmaf(p, f, 2.4022651e-1f);
    p = fmaf(p, f, 6.9314718e-1f);
    p = fmaf(p, f, 1.0f);
    float s = __int_as_float(((int)n + 127) << 23);
    return p * s;
}

// pi(m) = (m%4)*4 + m/4 applied within a 16-aligned block
__device__ __forceinline__ int perm16(int c) {
    return (c & ~15) + ((c & 3) * 4) + ((c & 15) >> 2);
}

// ============================================================================
// Pre-pass: tf32-round AND k-chunk-permute all three GEMM inputs.
// ============================================================================
#define N4_X  ((B_*S_*E_) / 4)
#define N4_WQ ((3*E_*E_) / 4)
#define N4_WP ((E_*E_) / 4)
#define N4_ALL (N4_X + N4_WQ + N4_WP)

__global__ void round_perm_all(const float* __restrict__ x,
                               const float* __restrict__ wq,
                               const float* __restrict__ wp)
{
    int f = blockIdx.x * blockDim.x + threadIdx.x;
    const int stride = gridDim.x * blockDim.x;
    for (; f < N4_ALL; f += stride) {
        const float* s;
        float4* d;
        int i = f;
        if (i < N4_X)               { s = x;  d = (float4*)g_Xr; }
        else if (i < N4_X + N4_WQ)  { i -= N4_X;         s = wq; d = (float4*)g_Wq; }
        else                        { i -= N4_X + N4_WQ; s = wp; d = (float4*)g_Wp; }
        const int t    = i & 3;
        const int base = (i >> 2) << 4;
        float4 v;
        v.x = tf32_rna(s[base + t]);
        v.y = tf32_rna(s[base + t + 4]);
        v.z = tf32_rna(s[base + t + 8]);
        v.w = tf32_rna(s[base + t + 12]);
        d[i] = v;
    }
}

// ============================================================================
// TF32 warp-MMA GEMM (round-8 verified): CTA 128x64, 8 warps 4x2, warp 32x32,
// 4-stage cp.async, BK=16, 3 CTAs/SM.
// ============================================================================
template<bool APERM> struct GeoT;
template<> struct GeoT<true>  { static const int ASTR = 16; };
template<> struct GeoT<false> { static const int ASTR = 20; };

#define NSTG 4

template<bool APERM>
__device__ __forceinline__ void gemm_fill(uint32_t smu, const float* __restrict__ Ab,
                                          const float* __restrict__ Bb,
                                          int stage, int chunk, int tid)
{
    const int ASTR = GeoT<APERM>::ASTR;
    const int BROW = 128 * ASTR;
    const int STGF = BROW + 64 * 16;
#pragma unroll
    for (int j = 0; j < 3; j++) {
        const int o = tid + 256 * j;
        const int r = o >> 2;
        const int q = (o & 3) * 4;
        const float* src;
        uint32_t off;
        if (r < 128) {
            src = Ab + (size_t)r * 1024 + chunk * 16 + q;
            off = (uint32_t)(stage * STGF + r * ASTR + q);
        } else {
            src = Bb + (size_t)(r - 128) * 1024 + chunk * 16 + q;
            off = (uint32_t)(stage * STGF + BROW + (r - 128) * 16 + q);
        }
        cp16(smu + off * 4, src);
    }
}

template<bool APERM>
__device__ __forceinline__ void gemm_tf32_pipe(const float* __restrict__ A,
                                               const float* __restrict__ Bm,
                                               int m0, int n0, float4 acc[2][4])
{
    const int ASTR = GeoT<APERM>::ASTR;
    const int BROW = 128 * ASTR;
    const int STGF = BROW + 64 * 16;

    extern __shared__ float sm[];
    const uint32_t smu = smem_u32(sm);
    const int tid  = threadIdx.x;
    const int lane = tid & 31;
    const int warp = tid >> 5;
    const int wm = (warp >> 1) * 32;
    const int wn = (warp & 1) * 32;
    const int g  = lane >> 2;
    const int t  = lane & 3;

    const float* Ab = A  + (size_t)m0 * 1024;
    const float* Bb = Bm + (size_t)n0 * 1024;

#pragma unroll
    for (int am = 0; am < 2; am++)
#pragma unroll
        for (int an = 0; an < 4; an++)
            acc[am][an] = make_float4(0.f, 0.f, 0.f, 0.f);

#pragma unroll
    for (int s = 0; s < NSTG - 1; s++) {
        gemm_fill<APERM>(smu, Ab, Bb, s, s, tid);
        CP_COMMIT();
    }

    for (int c = 0; c < 64; ++c) {
        CP_WAIT2();
        __syncthreads();

        if (c + 3 < 64)
            gemm_fill<APERM>(smu, Ab, Bb, (c + 3) & 3, c + 3, tid);
        CP_COMMIT();

        const float* st = sm + (c & 3) * STGF;

        float4 vb[4];
#pragma unroll
        for (int an = 0; an < 4; an++)
            vb[an] = *(const float4*)(st + BROW + (wn + an * 8 + g) * 16 + 4 * t);

        if (APERM) {
            float4 vaL[2], vaH[2];
#pragma unroll
            for (int am = 0; am < 2; am++) {
                vaL[am] = *(const float4*)(st + (wm + am * 16 + g)     * 16 + 4 * t);
                vaH[am] = *(const float4*)(st + (wm + am * 16 + g + 8) * 16 + 4 * t);
            }
#pragma unroll
            for (int am = 0; am < 2; am++)
#pragma unroll
                for (int an = 0; an < 4; an++) {
                    mma_tf32(acc[am][an],
                             __float_as_uint(vaL[am].x), __float_as_uint(vaH[am].x),
                             __float_as_uint(vaL[am].y), __float_as_uint(vaH[am].y),
                             __float_as_uint(vb[an].x),  __float_as_uint(vb[an].y));
                    mma_tf32(acc[am][an],
                             __float_as_uint(vaL[am].z), __float_as_uint(vaH[am].z),
                             __float_as_uint(vaL[am].w), __float_as_uint(vaH[am].w),
                             __float_as_uint(vb[an].z),  __float_as_uint(vb[an].w));
                }
        } else {
            uint32_t af[2][2][4];
#pragma unroll
            for (int ks = 0; ks < 2; ++ks)
#pragma unroll
                for (int am = 0; am < 2; am++) {
                    const float* p = st + (wm + am * 16 + g) * ASTR + ks * 8 + t;
                    af[ks][am][0] = __float_as_uint(p[0]);
                    af[ks][am][1] = __float_as_uint(p[8 * ASTR]);
                    af[ks][am][2] = __float_as_uint(p[4]);
                    af[ks][am][3] = __float_as_uint(p[8 * ASTR + 4]);
                }
#pragma unroll
            for (int am = 0; am < 2; am++)
#pragma unroll
                for (int an = 0; an < 4; an++) {
                    mma_tf32(acc[am][an],
                             af[0][am][0], af[0][am][1], af[0][am][2], af[0][am][3],
                             __float_as_uint(vb[an].x), __float_as_uint(vb[an].y));
                    mma_tf32(acc[am][an],
                             af[1][am][0], af[1][am][1], af[1][am][2], af[1][am][3],
                             __float_as_uint(vb[an].z), __float_as_uint(vb[an].w));
                }
        }
    }
}

#define QKV_SMEM_BYTES  (NSTG * (128*16 + 64*16) * 4)   // 49152
#define PROJ_SMEM_BYTES (NSTG * (128*20 + 64*16) * 4)   // 57344

// ---------------------------------------------------------------------------
// Kernel 1: QKV GEMM. grid (48, 32). Q natural; K d-permuted; V transposed
// (b,h,d,s) with s-permutation. Same values, relaid for attention LDS.128.
// ---------------------------------------------------------------------------
#define QSCALE 0.18033688011112042f   // 0.125 * log2(e)

__global__ void __launch_bounds__(256, 3) qkv_mma()
{
    const int m0 = blockIdx.y * 128;
    const int n0 = blockIdx.x * 64;
    float4 acc[2][4];
    gemm_tf32_pipe<true>(g_Xr, g_Wq, m0, n0, acc);

    const int lane = threadIdx.x & 31;
    const int warp = threadIdx.x >> 5;
    const int wm = (warp >> 1) * 32;
    const int wn = (warp & 1) * 32;
    const int g  = lane >> 2;
    const int t  = lane & 3;

#pragma unroll
    for (int an = 0; an < 4; an++) {
        const int ng  = n0 + wn + an * 8;        // n = h*192 + sel*64 + d
        const int grp = ng >> 6;
        const int h   = grp / 3;
        const int sel = grp - 3 * h;
        const int d0  = (ng & 63) + t * 2;       // first of 2 head-dim cols
        const float sc = (sel == 0) ? QSCALE : 1.0f;
#pragma unroll
        for (int am = 0; am < 2; am++) {
#pragma unroll
            for (int half = 0; half < 2; half++) {
                const int m = m0 + wm + am * 16 + g + half * 8;
                const int b = m >> 11;
                const int s = m & 2047;
                const float vx = tf32_rna((half ? acc[am][an].z : acc[am][an].x) * sc);
                const float vy = tf32_rna((half ? acc[am][an].w : acc[am][an].y) * sc);
                const size_t bh = (size_t)(b * 16 + h);
                if (sel == 0) {
                    *(float2*)(g_Q + (bh * 2048 + s) * 64 + d0) = make_float2(vx, vy);
                } else if (sel == 1) {
                    float* kp = g_K + (bh * 2048 + s) * 64;
                    kp[perm16(d0)]     = vx;
                    kp[perm16(d0 + 1)] = vy;
                } else {
                    const int sp = perm16(s);
                    float* vp = g_V + (bh * 64 + d0) * 2048;
                    vp[sp]        = vx;
                    vp[2048 + sp] = vy;
                }
            }
        }
    }
}

// ---------------------------------------------------------------------------
// Kernel 3: output projection. grid (16, 32). A = g_O (unpermuted).
// ---------------------------------------------------------------------------
__global__ void __launch_bounds__(256, 3) proj_mma(const float* __restrict__ bias,
                                                   float* __restrict__ out)
{
    const int m0 = blockIdx.y * 128;
    const int n0 = blockIdx.x * 64;
    float4 acc[2][4];
    gemm_tf32_pipe<false>(g_O, g_Wp, m0, n0, acc);

    const int lane = threadIdx.x & 31;
    const int warp = threadIdx.x >> 5;
    const int wm = (warp >> 1) * 32;
    const int wn = (warp & 1) * 32;
    const int g  = lane >> 2;
    const int t  = lane & 3;

#pragma unroll
    for (int an = 0; an < 4; an++) {
        const int ng = n0 + wn + an * 8 + t * 2;
        const float2 bi = *(const float2*)(bias + ng);
#pragma unroll
        for (int am = 0; am < 2; am++) {
#pragma unroll
            for (int half = 0; half < 2; half++) {
                const int m = m0 + wm + am * 16 + g + half * 8;
                float2 v;
                v.x = (half ? acc[am][an].z : acc[am][an].x) + bi.x;
                v.y = (half ? acc[am][an].w : acc[am][an].y) + bi.y;
                *(float2*)(out + (size_t)m * 1024 + ng) = v;
            }
        }
    }
}

// ============================================================================
// Kernel 2: tensor-core causal flash attention, vectorized fragment loads.
// K smem [2][64 s][80] (d permuted in global); V smem [2][64 d][80] (VT,
// s permuted in global). Stride 80 (=16 mod 32): LDS.128 conflict-free.
// ============================================================================
#define KVSTR 80
#define KBUF  (64*KVSTR)            // 5120
#define OFF_V (2*KBUF)              // 10240
#define VBUF  (64*KVSTR)
#define OFF_P (OFF_V + 2*VBUF)      // 20480
#define PSTRD 68
#define FA_SMEM_BYTES ((OFF_P + 128*PSTRD) * 4)   // 116736

__global__ void __launch_bounds__(256, 1) flash_attn_tc()
{
    extern __shared__ float sm[];
    const uint32_t smu = smem_u32(sm);
    const int tid  = threadIdx.x;
    const int lane = tid & 31;
    const int warp = tid >> 5;
    const int g  = lane >> 2;
    const int t4 = lane & 3;
    const int qt = 15 - (int)blockIdx.x;
    const int bh = blockIdx.y;
    const int q0 = qt * 128;
    const int wr = warp * 16;
    const int tmax = 2 * qt + 1;

    const float* Qg = g_Q + (size_t)bh * S_ * 64;
    const float* Kg = g_K + (size_t)bh * S_ * 64;
    const float* Vg = g_V + (size_t)bh * 64 * S_;   // transposed [d][s]

    // K/V tile 0: K rows = s (d contiguous), V rows = d (s contiguous)
    {
        const int r = tid >> 2;
        const int c = (tid & 3) * 16;
        const float* ks = Kg + (size_t)r * 64 + c;
        const float* vs = Vg + (size_t)r * 2048 + c;   // kv0 = 0
        const uint32_t kd = smu + (uint32_t)(r * KVSTR + c) * 4;
        const uint32_t vd = smu + (uint32_t)(OFF_V + r * KVSTR + c) * 4;
#pragma unroll
        for (int j = 0; j < 4; j++) {
            cp16(kd + j * 16, ks + j * 4);
            cp16(vd + j * 16, vs + j * 4);
        }
        CP_COMMIT();
    }

    // stage Q tile into P region (coalesced), then pull warp fragments
    {
        const int r  = tid >> 1;
        const int c0 = (tid & 1) * 32;
        const float* src = Qg + (size_t)(q0 + r) * 64 + c0;
        float* dst = sm + OFF_P + r * PSTRD + c0;
#pragma unroll
        for (int j = 0; j < 8; j++)
            *(float4*)(dst + j * 4) = *(const float4*)(src + j * 4);
    }
    __syncthreads();

    uint32_t qf[8][4];
#pragma unroll
    for (int kk = 0; kk < 8; kk++) {
        const float* p = sm + OFF_P + (wr + g) * PSTRD + kk * 8 + t4;
        qf[kk][0] = __float_as_uint(p[0]);
        qf[kk][1] = __float_as_uint(p[8 * PSTRD]);
        qf[kk][2] = __float_as_uint(p[4]);
        qf[kk][3] = __float_as_uint(p[8 * PSTRD + 4]);
    }

    float m2[2] = {-1e30f, -1e30f};
    float l2[2] = {0.f, 0.f};
    float4 of[8];
#pragma unroll
    for (int an = 0; an < 8; an++) of[an] = make_float4(0.f, 0.f, 0.f, 0.f);

    for (int t = 0; t <= tmax; t++) {
        CP_WAIT0();
        __syncthreads();

        if (t < tmax) {
            const int kv1 = (t + 1) * 64;
            const int buf = (t + 1) & 1;
            const int r = tid >> 2;
            const int c = (tid & 3) * 16;
            const float* ks = Kg + (size_t)(kv1 + r) * 64 + c;
            const float* vs = Vg + (size_t)r * 2048 + kv1 + c;
            const uint32_t kd = smu + (uint32_t)(buf * KBUF + r * KVSTR + c) * 4;
            const uint32_t vd = smu + (uint32_t)(OFF_V + buf * VBUF + r * KVSTR + c) * 4;
#pragma unroll
            for (int j = 0; j < 4; j++) {
                cp16(kd + j * 16, ks + j * 4);
                cp16(vd + j * 16, vs + j * 4);
            }
            CP_COMMIT();
        }

        const int kv0 = t * 64;
        if (kv0 <= q0 + wr + 15) {
            const float* smK = sm + (t & 1) * KBUF;
            const float* smV = sm + OFF_V + (t & 1) * VBUF;

            // S = Q @ K^T — K fragments via LDS.128 (d permuted)
            float4 sf[8];
#pragma unroll
            for (int an = 0; an < 8; an++) sf[an] = make_float4(0.f, 0.f, 0.f, 0.f);
#pragma unroll
            for (int b = 0; b < 4; b++) {
#pragma unroll
                for (int an = 0; an < 8; an++) {
                    const float4 kv4 = *(const float4*)(smK + (an * 8 + g) * KVSTR + 16 * b + 4 * t4);
                    mma_tf32(sf[an], qf[2*b][0], qf[2*b][1], qf[2*b][2], qf[2*b][3],
                             __float_as_uint(kv4.x), __float_as_uint(kv4.y));
                    mma_tf32(sf[an], qf[2*b+1][0], qf[2*b+1][1], qf[2*b+1][2], qf[2*b+1][3],
                             __float_as_uint(kv4.z), __float_as_uint(kv4.w));
                }
            }

            if (kv0 + 63 > q0 + wr) {
                const int r0 = q0 + wr + g;
                const int r1 = r0 + 8;
#pragma unroll
                for (int an = 0; an < 8; an++) {
                    const int col = kv0 + an * 8 + 2 * t4;
                    if (col     > r0) sf[an].x = -1e30f;
                    if (col + 1 > r0) sf[an].y = -1e30f;
                    if (col     > r1) sf[an].z = -1e30f;
                    if (col + 1 > r1) sf[an].w = -1e30f;
                }
            }

            float mt0 = -1e30f, mt1 = -1e30f;
#pragma unroll
            for (int an = 0; an < 8; an++) {
                mt0 = fmaxf(mt0, fmaxf(sf[an].x, sf[an].y));
                mt1 = fmaxf(mt1, fmaxf(sf[an].z, sf[an].w));
            }
            mt0 = fmaxf(mt0, __shfl_xor_sync(0xffffffffu, mt0, 1));
            mt0 = fmaxf(mt0, __shfl_xor_sync(0xffffffffu, mt0, 2));
            mt1 = fmaxf(mt1, __shfl_xor_sync(0xffffffffu, mt1, 1));
            mt1 = fmaxf(mt1, __shfl_xor_sync(0xffffffffu, mt1, 2));

            const float mn0 = fmaxf(m2[0], mt0);
            const float mn1 = fmaxf(m2[1], mt1);
            const float a0 = exp2p(m2[0] - mn0);
            const float a1 = exp2p(m2[1] - mn1);
            m2[0] = mn0; m2[1] = mn1;

            float s0 = 0.f, s1 = 0.f;
#pragma unroll
            for (int an = 0; an < 8; an++) {
                sf[an].x = tf32_rna(exp2p(sf[an].x - mn0));
                sf[an].y = tf32_rna(exp2p(sf[an].y - mn0));
                sf[an].z = tf32_rna(exp2p(sf[an].z - mn1));
                sf[an].w = tf32_rna(exp2p(sf[an].w - mn1));
                s0 += sf[an].x + sf[an].y;
                s1 += sf[an].z + sf[an].w;
            }
            s0 += __shfl_xor_sync(0xffffffffu, s0, 1);
            s0 += __shfl_xor_sync(0xffffffffu, s0, 2);
            s1 += __shfl_xor_sync(0xffffffffu, s1, 1);
            s1 += __shfl_xor_sync(0xffffffffu, s1, 2);
            l2[0] = l2[0] * a0 + s0;
            l2[1] = l2[1] * a1 + s1;

#pragma unroll
            for (int an = 0; an < 8; an++) {
                of[an].x *= a0; of[an].y *= a0;
                of[an].z *= a1; of[an].w *= a1;
            }

            // P -> smem (own rows)
            {
                float* pp = sm + OFF_P + (wr + g) * PSTRD;
#pragma unroll
                for (int an = 0; an < 8; an++) {
                    *(float2*)(pp + an * 8 + 2 * t4) = make_float2(sf[an].x, sf[an].y);
                    *(float2*)(pp + 8 * PSTRD + an * 8 + 2 * t4) = make_float2(sf[an].z, sf[an].w);
                }
            }
            __syncwarp();

            // O += P @ V — V^T fragments via LDS.128 (s permuted); P natural,
            // k-pairing matches the permuted float4 positionally.
#pragma unroll
            for (int b = 0; b < 4; b++) {
                const float* ap = sm + OFF_P + (wr + g) * PSTRD + 16 * b + t4;
                const uint32_t A00 = __float_as_uint(ap[0]);
                const uint32_t A01 = __float_as_uint(ap[8 * PSTRD]);
                const uint32_t A02 = __float_as_uint(ap[4]);
                const uint32_t A03 = __float_as_uint(ap[8 * PSTRD + 4]);
                const uint32_t A10 = __float_as_uint(ap[8]);
                const uint32_t A11 = __float_as_uint(ap[8 * PSTRD + 8]);
                const uint32_t A12 = __float_as_uint(ap[12]);
                const uint32_t A13 = __float_as_uint(ap[8 * PSTRD + 12]);
#pragma unroll
                for (int an = 0; an < 8; an++) {
                    const float4 vv = *(const float4*)(smV + (an * 8 + g) * KVSTR + 16 * b + 4 * t4);
                    mma_tf32(of[an], A00, A01, A02, A03,
                             __float_as_uint(vv.x), __float_as_uint(vv.y));
                    mma_tf32(of[an], A10, A11, A12, A13,
                             __float_as_uint(vv.z), __float_as_uint(vv.w));
                }
            }
        }
        __syncthreads();
    }

    const int b = bh >> 4;
    const int h = bh & 15;
    const float i0 = 1.0f / l2[0];
    const float i1 = 1.0f / l2[1];
    const int r0 = q0 + wr + g;
    const int r1 = r0 + 8;
    float* o0 = g_O + ((size_t)b * 2048 + r0) * 1024 + h * 64;
    float* o1 = g_O + ((size_t)b * 2048 + r1) * 1024 + h * 64;
#pragma unroll
    for (int an = 0; an < 8; an++) {
        const int d = an * 8 + 2 * t4;
        *(float2*)(o0 + d) = make_float2(tf32_rna(of[an].x * i0), tf32_rna(of[an].y * i0));
        *(float2*)(o1 + d) = make_float2(tf32_rna(of[an].z * i1), tf32_rna(of[an].w * i1));
    }
}

// ---------------------------------------------------------------------------
extern "C" void kernel_launch(void* const* d_in, const int* in_sizes, int n_in,
                              void* d_out, int out_size)
{
    const float* x      = (const float*)d_in[0];  // (2,2048,1024)
    const float* w_qkv  = (const float*)d_in[1];  // (3072,1024)
    const float* w_proj = (const float*)d_in[2];  // (1024,1024)
    const float* b_proj = (const float*)d_in[3];  // (1024,)
    float* out = (float*)d_out;

    cudaFuncSetAttribute(flash_attn_tc, cudaFuncAttributeMaxDynamicSharedMemorySize,
                         FA_SMEM_BYTES);
    cudaFuncSetAttribute(qkv_mma, cudaFuncAttributeMaxDynamicSharedMemorySize,
                         QKV_SMEM_BYTES);
    cudaFuncSetAttribute(proj_mma, cudaFuncAttributeMaxDynamicSharedMemorySize,
                         PROJ_SMEM_BYTES);

    round_perm_all<<<592, 256>>>(x, w_qkv, w_proj);

    qkv_mma<<<dim3(48, 32), 256, QKV_SMEM_BYTES>>>();
    flash_attn_tc<<<dim3(16, 32), 256, FA_SMEM_BYTES>>>();
    proj_mma<<<dim3(16, 32), 256, PROJ_SMEM_BYTES>>>(b_proj, out);
}

// round 10
// speedup vs baseline: 1.1677x; 1.0304x over previous
#include <cuda_runtime.h>
#include <math.h>
#include <stdint.h>

#define B_  2
#define S_  2048
#define E_  1024
#define H_  16
#define HD_ 64

// Scratch (allocation-free: __device__ globals)
__device__ float g_Q[B_*H_*S_*HD_];   // (b,h,s,d) tf32-rounded, scaled 0.125*log2(e)
__device__ float g_K[B_*H_*S_*HD_];   // (b,h,s,d) tf32-rounded, d 16-block-permuted
__device__ float g_V[B_*H_*S_*HD_];   // (b,h,d,s) TRANSPOSED, s 16-block-permuted
__device__ float g_O[B_*S_*E_];       // attention out, tf32-rounded, d 16-block-permuted
__device__ float g_Xr[B_*S_*E_];      // tf32-rounded x, k-chunk permuted
__device__ float g_Wq[3*E_*E_];       // tf32-rounded w_qkv, k-chunk permuted
__device__ float g_Wp[E_*E_];         // tf32-rounded w_proj, k-chunk permuted

// ============================================================================
// PTX helpers (plain sm_80+ ISA)
// ============================================================================
__device__ __forceinline__ float tf32_rna(float x) {
    uint32_t r;
    asm("cvt.rna.tf32.f32 %0, %1;" : "=r"(r) : "f"(x));
    return __uint_as_float(r);
}

__device__ __forceinline__ void mma_tf32(float4& d,
                                         uint32_t a0, uint32_t a1, uint32_t a2, uint32_t a3,
                                         uint32_t b0, uint32_t b1)
{
    asm volatile(
        "mma.sync.aligned.m16n8k8.row.col.f32.tf32.tf32.f32 "
        "{%0,%1,%2,%3}, {%4,%5,%6,%7}, {%8,%9}, {%0,%1,%2,%3};"
        : "+f"(d.x), "+f"(d.y), "+f"(d.z), "+f"(d.w)
        : "r"(a0), "r"(a1), "r"(a2), "r"(a3), "r"(b0), "r"(b1));
}

__device__ __forceinline__ uint32_t smem_u32(const void* p) {
    uint32_t a;
    asm("{ .reg .u64 tmp; cvta.to.shared.u64 tmp, %1; cvt.u32.u64 %0, tmp; }"
        : "=r"(a) : "l"(p));
    return a;
}

__device__ __forceinline__ void cp16(uint32_t dst, const void* src) {
    asm volatile("cp.async.cg.shared.global [%0], [%1], 16;"
                 :: "r"(dst), "l"(src) : "memory");
}
#define CP_COMMIT() asm volatile("cp.async.commit_group;" ::: "memory")
#define CP_WAIT1()  asm volatile("cp.async.wait_group 1;" ::: "memory")

// exp2 on the FMA pipe: degree-6 poly on f in [-0.5, 0.5], rel err ~1.2e-7.
__device__ __forceinline__ float exp2p(float x) {
    x = fmaxf(x, -126.0f);
    float n = rintf(x);
    float f = x - n;
    float p = 1.5403530e-4f;
    p = fmaf(p, f, 1.3333558e-3f);
    p = fmaf(p, f, 9.6181291e-3f);
    p = fmaf(p, f, 5.5504109e-2f);
    p = fmaf(p, f, 2.4022651e-1f);
    p = fmaf(p, f, 6.9314718e-1f);
    p = fmaf(p, f, 1.0f);
    float s = __int_as_float(((int)n + 127) << 23);
    return p * s;
}

// pi(m) = (m%4)*4 + m/4 applied within a 16-aligned block (self-inverse)
__device__ __forceinline__ int perm16(int c) {
    return (c & ~15) + ((c & 3) * 4) + ((c & 15) >> 2);
}

// ============================================================================
// Pre-pass: tf32-round AND k-chunk-permute all three GEMM inputs.
// ============================================================================
#define N4_X  ((B_*S_*E_) / 4)
#define N4_WQ ((3*E_*E_) / 4)
#define N4_WP ((E_*E_) / 4)
#define N4_ALL (N4_X + N4_WQ + N4_WP)

__global__ void round_perm_all(const float* __restrict__ x,
                               const float* __restrict__ wq,
                               const float* __restrict__ wp)
{
    int f = blockIdx.x * blockDim.x + threadIdx.x;
    const int stride = gridDim.x * blockDim.x;
    for (; f < N4_ALL; f += stride) {
        const float* s;
        float4* d;
        int i = f;
        if (i < N4_X)               { s = x;  d = (float4*)g_Xr; }
        else if (i < N4_X + N4_WQ)  { i -= N4_X;         s = wq; d = (float4*)g_Wq; }
        else                        { i -= N4_X + N4_WQ; s = wp; d = (float4*)g_Wp; }
        const int t    = i & 3;
        const int base = (i >> 2) << 4;
        float4 v;
        v.x = tf32_rna(s[base + t]);
        v.y = tf32_rna(s[base + t + 4]);
        v.z = tf32_rna(s[base + t + 8]);
        v.w = tf32_rna(s[base + t + 12]);
        d[i] = v;
    }
}

// ============================================================================
// TF32 warp-MMA GEMM, BK=32 / 3-stage cp.async / ONE sync per 32-k chunk.
// CTA 128x64, 8 warps 4x2, warp 32x32. Both A and B k-chunk permuted.
// Stage = two 16-k halves, each [A 128x16 | B 64x16] (round-8 layout).
// ============================================================================
#define NSTG3 3
#define HALF_F 3072                       // 128*16 + 64*16
#define STGF32 (2*HALF_F)                 // 6144 floats
#define GEMM_SMEM_BYTES (NSTG3*STGF32*4)  // 73728

__device__ __forceinline__ void gemm_fill32(uint32_t smu, const float* __restrict__ Ab,
                                            const float* __restrict__ Bb,
                                            int stage, int chunk, int tid)
{
#pragma unroll
    for (int j = 0; j < 6; j++) {
        const int o = tid + 256 * j;      // 0..1535 float4 slots
        const int h = (o >> 2) & 1;       // k-half
        const int r = o >> 3;             // 0..191
        const int q = (o & 3) * 4;
        const float* src;
        uint32_t off;
        if (r < 128) {
            src = Ab + (size_t)r * 1024 + chunk * 32 + h * 16 + q;
            off = (uint32_t)(r * 16);
        } else {
            src = Bb + (size_t)(r - 128) * 1024 + chunk * 32 + h * 16 + q;
            off = (uint32_t)(2048 + (r - 128) * 16);
        }
        cp16(smu + (uint32_t)(stage * STGF32 + h * HALF_F + off + q) * 4, src);
    }
}

__device__ __forceinline__ void gemm_tf32_pipe32(const float* __restrict__ A,
                                                 const float* __restrict__ Bm,
                                                 int m0, int n0, float4 acc[2][4])
{
    extern __shared__ float sm[];
    const uint32_t smu = smem_u32(sm);
    const int tid  = threadIdx.x;
    const int lane = tid & 31;
    const int warp = tid >> 5;
    const int wm = (warp >> 1) * 32;
    const int wn = (warp & 1) * 32;
    const int g  = lane >> 2;
    const int t  = lane & 3;

    const float* Ab = A  + (size_t)m0 * 1024;
    const float* Bb = Bm + (size_t)n0 * 1024;

#pragma unroll
    for (int am = 0; am < 2; am++)
#pragma unroll
        for (int an = 0; an < 4; an++)
            acc[am][an] = make_float4(0.f, 0.f, 0.f, 0.f);

    gemm_fill32(smu, Ab, Bb, 0, 0, tid);
    CP_COMMIT();
    gemm_fill32(smu, Ab, Bb, 1, 1, tid);
    CP_COMMIT();

    int stage = 0;
    for (int c = 0; c < 32; ++c) {
        CP_WAIT1();            // chunk c resident (c+1 may still be in flight)
        __syncthreads();       // visibility + buffer-retire (single barrier)

        if (c + 2 < 32)
            gemm_fill32(smu, Ab, Bb, (stage + 2 >= 3 ? stage - 1 : stage + 2), c + 2, tid);
        CP_COMMIT();           // uniform commit keeps wait_group(1) exact

#pragma unroll
        for (int h = 0; h < 2; h++) {
            const float* st = sm + stage * STGF32 + h * HALF_F;

            float4 vb[4];
#pragma unroll
            for (int an = 0; an < 4; an++)
                vb[an] = *(const float4*)(st + 2048 + (wn + an * 8 + g) * 16 + 4 * t);

            float4 vaL[2], vaH[2];
#pragma unroll
            for (int am = 0; am < 2; am++) {
                vaL[am] = *(const float4*)(st + (wm + am * 16 + g)     * 16 + 4 * t);
                vaH[am] = *(const float4*)(st + (wm + am * 16 + g + 8) * 16 + 4 * t);
            }
#pragma unroll
            for (int am = 0; am < 2; am++)
#pragma unroll
                for (int an = 0; an < 4; an++) {
                    mma_tf32(acc[am][an],
                             __float_as_uint(vaL[am].x), __float_as_uint(vaH[am].x),
                             __float_as_uint(vaL[am].y), __float_as_uint(vaH[am].y),
                             __float_as_uint(vb[an].x),  __float_as_uint(vb[an].y));
                    mma_tf32(acc[am][an],
                             __float_as_uint(vaL[am].z), __float_as_uint(vaH[am].z),
                             __float_as_uint(vaL[am].w), __float_as_uint(vaH[am].w),
                             __float_as_uint(vb[an].z),  __float_as_uint(vb[an].w));
                }
        }
        stage = (stage == 2) ? 0 : stage + 1;
    }
}

// ---------------------------------------------------------------------------
// Kernel 1: QKV GEMM. grid (48, 32). Q natural; K d-permuted; V transposed
// (b,h,d,s) s-permuted. Q pre-scaled by 0.125*log2(e).
// ---------------------------------------------------------------------------
#define QSCALE 0.18033688011112042f   // 0.125 * log2(e)

__global__ void __launch_bounds__(256, 3) qkv_mma()
{
    const int m0 = blockIdx.y * 128;
    const int n0 = blockIdx.x * 64;
    float4 acc[2][4];
    gemm_tf32_pipe32(g_Xr, g_Wq, m0, n0, acc);

    const int lane = threadIdx.x & 31;
    const int warp = threadIdx.x >> 5;
    const int wm = (warp >> 1) * 32;
    const int wn = (warp & 1) * 32;
    const int g  = lane >> 2;
    const int t  = lane & 3;

#pragma unroll
    for (int an = 0; an < 4; an++) {
        const int ng  = n0 + wn + an * 8;        // n = h*192 + sel*64 + d
        const int grp = ng >> 6;
        const int h   = grp / 3;
        const int sel = grp - 3 * h;
        const int d0  = (ng & 63) + t * 2;
        const float sc = (sel == 0) ? QSCALE : 1.0f;
#pragma unroll
        for (int am = 0; am < 2; am++) {
#pragma unroll
            for (int half = 0; half < 2; half++) {
                const int m = m0 + wm + am * 16 + g + half * 8;
                const int b = m >> 11;
                const int s = m & 2047;
                const float vx = tf32_rna((half ? acc[am][an].z : acc[am][an].x) * sc);
                const float vy = tf32_rna((half ? acc[am][an].w : acc[am][an].y) * sc);
                const size_t bh = (size_t)(b * 16 + h);
                if (sel == 0) {
                    *(float2*)(g_Q + (bh * 2048 + s) * 64 + d0) = make_float2(vx, vy);
                } else if (sel == 1) {
                    float* kp = g_K + (bh * 2048 + s) * 64;
                    kp[perm16(d0)]     = vx;
                    kp[perm16(d0 + 1)] = vy;
                } else {
                    const int sp = perm16(s);
                    float* vp = g_V + (bh * 64 + d0) * 2048;
                    vp[sp]        = vx;
                    vp[2048 + sp] = vy;
                }
            }
        }
    }
}

// ---------------------------------------------------------------------------
// Kernel 3: output projection. grid (16, 32). A = g_O (d-permuted, matching
// the k-chunk-permuted g_Wp — same both-sides pairing as qkv).
// ---------------------------------------------------------------------------
__global__ void __launch_bounds__(256, 3) proj_mma(const float* __restrict__ bias,
                                                   float* __restrict__ out)
{
    const int m0 = blockIdx.y * 128;
    const int n0 = blockIdx.x * 64;
    float4 acc[2][4];
    gemm_tf32_pipe32(g_O, g_Wp, m0, n0, acc);

    const int lane = threadIdx.x & 31;
    const int warp = threadIdx.x >> 5;
    const int wm = (warp >> 1) * 32;
    const int wn = (warp & 1) * 32;
    const int g  = lane >> 2;
    const int t  = lane & 3;

#pragma unroll
    for (int an = 0; an < 4; an++) {
        const int ng = n0 + wn + an * 8 + t * 2;
        const float2 bi = *(const float2*)(bias + ng);
#pragma unroll
        for (int am = 0; am < 2; am++) {
#pragma unroll
            for (int half = 0; half < 2; half++) {
                const int m = m0 + wm + am * 16 + g + half * 8;
                float2 v;
                v.x = (half ? acc[am][an].z : acc[am][an].x) + bi.x;
                v.y = (half ? acc[am][an].w : acc[am][an].y) + bi.y;
                *(float2*)(out + (size_t)m * 1024 + ng) = v;
            }
        }
    }
}

// ============================================================================
// Kernel 2: tensor-core causal flash attention.
// TRIPLE-buffered K/V (rotation mod 3) -> ONE __syncthreads per tile.
// K smem [3][64][80] (d permuted); V smem [3][64][80] (transposed, s
// permuted). Stride 80: LDS.128 conflict-free per quarter-warp.
// ============================================================================
#define KVSTR 80
#define KVBUF (64*KVSTR)            // 5120 floats
#define OFF_V (3*KVBUF)             // 15360
#define OFF_P (OFF_V + 3*KVBUF)     // 30720
#define PSTRD 68
#define FA_SMEM_BYTES ((OFF_P + 128*PSTRD) * 4)   // 157696

__global__ void __launch_bounds__(256, 1) flash_attn_tc()
{
    extern __shared__ float sm[];
    const uint32_t smu = smem_u32(sm);
    const int tid  = threadIdx.x;
    const int lane = tid & 31;
    const int warp = tid >> 5;
    const int g  = lane >> 2;
    const int t4 = lane & 3;
    const int qt = 15 - (int)blockIdx.x;
    const int bh = blockIdx.y;
    const int q0 = qt * 128;
    const int wr = warp * 16;
    const int tmax = 2 * qt + 1;     // >= 1 always

    const float* Qg = g_Q + (size_t)bh * S_ * 64;
    const float* Kg = g_K + (size_t)bh * S_ * 64;
    const float* Vg = g_V + (size_t)bh * 64 * S_;   // transposed [d][s]

    const int fr = tid >> 2;
    const int fc = (tid & 3) * 16;

    // prologue: prefetch tiles 0 and 1 (tmax >= 1 guaranteed)
#pragma unroll
    for (int pt = 0; pt < 2; pt++) {
        const int kv = pt * 64;
        const float* ks = Kg + (size_t)(kv + fr) * 64 + fc;
        const float* vs = Vg + (size_t)fr * 2048 + kv + fc;
        const uint32_t kd = smu + (uint32_t)(pt * KVBUF + fr * KVSTR + fc) * 4;
        const uint32_t vd = smu + (uint32_t)(OFF_V + pt * KVBUF + fr * KVSTR + fc) * 4;
#pragma unroll
        for (int j = 0; j < 4; j++) {
            cp16(kd + j * 16, ks + j * 4);
            cp16(vd + j * 16, vs + j * 4);
        }
        CP_COMMIT();
    }

    // stage Q tile into P region (coalesced), then pull warp fragments
    {
        const int r  = tid >> 1;
        const int c0 = (tid & 1) * 32;
        const float* src = Qg + (size_t)(q0 + r) * 64 + c0;
        float* dst = sm + OFF_P + r * PSTRD + c0;
#pragma unroll
        for (int j = 0; j < 8; j++)
            *(float4*)(dst + j * 4) = *(const float4*)(src + j * 4);
    }
    __syncthreads();

    uint32_t qf[8][4];
#pragma unroll
    for (int kk = 0; kk < 8; kk++) {
        const float* p = sm + OFF_P + (wr + g) * PSTRD + kk * 8 + t4;
        qf[kk][0] = __float_as_uint(p[0]);
        qf[kk][1] = __float_as_uint(p[8 * PSTRD]);
        qf[kk][2] = __float_as_uint(p[4]);
        qf[kk][3] = __float_as_uint(p[8 * PSTRD + 4]);
    }

    float m2[2] = {-1e30f, -1e30f};
    float l2[2] = {0.f, 0.f};
    float4 of[8];
#pragma unroll
    for (int an = 0; an < 8; an++) of[an] = make_float4(0.f, 0.f, 0.f, 0.f);

    int buf = 0;
    for (int t = 0; t <= tmax; t++) {
        CP_WAIT1();            // tile t resident (t+1 may be in flight)
        __syncthreads();       // single per-tile barrier

        if (t + 2 <= tmax) {   // prefetch tile t+2 into buffer (t+2)%3
            const int kv2 = (t + 2) * 64;
            const int b2  = (buf + 2 >= 3) ? buf - 1 : buf + 2;
            const float* ks = Kg + (size_t)(kv2 + fr) * 64 + fc;
            const float* vs = Vg + (size_t)fr * 2048 + kv2 + fc;
            const uint32_t kd = smu + (uint32_t)(b2 * KVBUF + fr * KVSTR + fc) * 4;
            const uint32_t vd = smu + (uint32_t)(OFF_V + b2 * KVBUF + fr * KVSTR + fc) * 4;
#pragma unroll
            for (int j = 0; j < 4; j++) {
                cp16(kd + j * 16, ks + j * 4);
                cp16(vd + j * 16, vs + j * 4);
            }
        }
        CP_COMMIT();           // uniform commit (possibly empty)

        const int kv0 = t * 64;
        if (kv0 <= q0 + wr + 15) {
            const float* smK = sm + buf * KVBUF;
            const float* smV = sm + OFF_V + buf * KVBUF;

            // S = Q @ K^T — K fragments via LDS.128 (d permuted)
            float4 sf[8];
#pragma unroll
            for (int an = 0; an < 8; an++) sf[an] = make_float4(0.f, 0.f, 0.f, 0.f);
#pragma unroll
            for (int b = 0; b < 4; b++) {
#pragma unroll
                for (int an = 0; an < 8; an++) {
                    const float4 kv4 = *(const float4*)(smK + (an * 8 + g) * KVSTR + 16 * b + 4 * t4);
                    mma_tf32(sf[an], qf[2*b][0], qf[2*b][1], qf[2*b][2], qf[2*b][3],
                             __float_as_uint(kv4.x), __float_as_uint(kv4.y));
                    mma_tf32(sf[an], qf[2*b+1][0], qf[2*b+1][1], qf[2*b+1][2], qf[2*b+1][3],
                             __float_as_uint(kv4.z), __float_as_uint(kv4.w));
                }
            }

            if (kv0 + 63 > q0 + wr) {
                const int r0 = q0 + wr + g;
                const int r1 = r0 + 8;
#pragma unroll
                for (int an = 0; an < 8; an++) {
                    const int col = kv0 + an * 8 + 2 * t4;
                    if (col     > r0) sf[an].x = -1e30f;
                    if (col + 1 > r0) sf[an].y = -1e30f;
                    if (col     > r1) sf[an].z = -1e30f;
                    if (col + 1 > r1) sf[an].w = -1e30f;
                }
            }

            float mt0 = -1e30f, mt1 = -1e30f;
#pragma unroll
            for (int an = 0; an < 8; an++) {
                mt0 = fmaxf(mt0, fmaxf(sf[an].x, sf[an].y));
                mt1 = fmaxf(mt1, fmaxf(sf[an].z, sf[an].w));
            }
            mt0 = fmaxf(mt0, __shfl_xor_sync(0xffffffffu, mt0, 1));
            mt0 = fmaxf(mt0, __shfl_xor_sync(0xffffffffu, mt0, 2));
            mt1 = fmaxf(mt1, __shfl_xor_sync(0xffffffffu, mt1, 1));
            mt1 = fmaxf(mt1, __shfl_xor_sync(0xffffffffu, mt1, 2));

            const float mn0 = fmaxf(m2[0], mt0);
            const float mn1 = fmaxf(m2[1], mt1);
            const float a0 = exp2p(m2[0] - mn0);
            const float a1 = exp2p(m2[1] - mn1);
            m2[0] = mn0; m2[1] = mn1;

            float s0 = 0.f, s1 = 0.f;
#pragma unroll
            for (int an = 0; an < 8; an++) {
                sf[an].x = tf32_rna(exp2p(sf[an].x - mn0));
                sf[an].y = tf32_rna(exp2p(sf[an].y - mn0));
                sf[an].z = tf32_rna(exp2p(sf[an].z - mn1));
                sf[an].w = tf32_rna(exp2p(sf[an].w - mn1));
                s0 += sf[an].x + sf[an].y;
                s1 += sf[an].z + sf[an].w;
            }
            s0 += __shfl_xor_sync(0xffffffffu, s0, 1);
            s0 += __shfl_xor_sync(0xffffffffu, s0, 2);
            s1 += __shfl_xor_sync(0xffffffffu, s1, 1);
            s1 += __shfl_xor_sync(0xffffffffu, s1, 2);
            l2[0] = l2[0] * a0 + s0;
            l2[1] = l2[1] * a1 + s1;

#pragma unroll
            for (int an = 0; an < 8; an++) {
                of[an].x *= a0; of[an].y *= a0;
                of[an].z *= a1; of[an].w *= a1;
            }

            // P -> smem (own rows only; cross-warp never touches them)
            {
                float* pp = sm + OFF_P + (wr + g) * PSTRD;
#pragma unroll
                for (int an = 0; an < 8; an++) {
                    *(float2*)(pp + an * 8 + 2 * t4) = make_float2(sf[an].x, sf[an].y);
                    *(float2*)(pp + 8 * PSTRD + an * 8 + 2 * t4) = make_float2(sf[an].z, sf[an].w);
                }
            }
            __syncwarp();

            // O += P @ V — V^T fragments via LDS.128 (s permuted)
#pragma unroll
            for (int b = 0; b < 4; b++) {
                const float* ap = sm + OFF_P + (wr + g) * PSTRD + 16 * b + t4;
                const uint32_t A00 = __float_as_uint(ap[0]);
                const uint32_t A01 = __float_as_uint(ap[8 * PSTRD]);
                const uint32_t A02 = __float_as_uint(ap[4]);
                const uint32_t A03 = __float_as_uint(ap[8 * PSTRD + 4]);
                const uint32_t A10 = __float_as_uint(ap[8]);
                const uint32_t A11 = __float_as_uint(ap[8 * PSTRD + 8]);
                const uint32_t A12 = __float_as_uint(ap[12]);
                const uint32_t A13 = __float_as_uint(ap[8 * PSTRD + 12]);
#pragma unroll
                for (int an = 0; an < 8; an++) {
                    const float4 vv = *(const float4*)(smV + (an * 8 + g) * KVSTR + 16 * b + 4 * t4);
                    mma_tf32(of[an], A00, A01, A02, A03,
                             __float_as_uint(vv.x), __float_as_uint(vv.y));
                    mma_tf32(of[an], A10, A11, A12, A13,
                             __float_as_uint(vv.z), __float_as_uint(vv.w));
                }
            }
        }
        buf = (buf == 2) ? 0 : buf + 1;
        // no bottom sync — 3-buffer rotation makes it unnecessary
    }

    // epilogue: normalize, tf32-round, write g_O d-PERMUTED (proj A layout)
    const int b = bh >> 4;
    const int h = bh & 15;
    const float i0 = 1.0f / l2[0];
    const float i1 = 1.0f / l2[1];
    const int r0 = q0 + wr + g;
    const int r1 = r0 + 8;
    float* o0 = g_O + ((size_t)b * 2048 + r0) * 1024 + h * 64;
    float* o1 = g_O + ((size_t)b * 2048 + r1) * 1024 + h * 64;
#pragma unroll
    for (int an = 0; an < 8; an++) {
        const int c0 = an * 8 + 2 * t4;
        const int p0 = perm16(c0);
        const int p1 = perm16(c0 + 1);
        o0[p0] = tf32_rna(of[an].x * i0);
        o0[p1] = tf32_rna(of[an].y * i0);
        o1[p0] = tf32_rna(of[an].z * i1);
        o1[p1] = tf32_rna(of[an].w * i1);
    }
}

// ---------------------------------------------------------------------------
extern "C" void kernel_launch(void* const* d_in, const int* in_sizes, int n_in,
                              void* d_out, int out_size)
{
    const float* x      = (const float*)d_in[0];  // (2,2048,1024)
    const float* w_qkv  = (const float*)d_in[1];  // (3072,1024)
    const float* w_proj = (const float*)d_in[2];  // (1024,1024)
    const float* b_proj = (const float*)d_in[3];  // (1024,)
    float* out = (float*)d_out;

    cudaFuncSetAttribute(flash_attn_tc, cudaFuncAttributeMaxDynamicSharedMemorySize,
                         FA_SMEM_BYTES);
    cudaFuncSetAttribute(qkv_mma, cudaFuncAttributeMaxDynamicSharedMemorySize,
                         GEMM_SMEM_BYTES);
    cudaFuncSetAttribute(proj_mma, cudaFuncAttributeMaxDynamicSharedMemorySize,
                         GEMM_SMEM_BYTES);

    round_perm_all<<<592, 256>>>(x, w_qkv, w_proj);

    qkv_mma<<<dim3(48, 32), 256, GEMM_SMEM_BYTES>>>();
    flash_attn_tc<<<dim3(16, 32), 256, FA_SMEM_BYTES>>>();
    proj_mma<<<dim3(16, 32), 256, GEMM_SMEM_BYTES>>>(b_proj, out);
}